// round 8
// baseline (speedup 1.0000x reference)
#include <cuda_runtime.h>
#include <cstdint>

#define EMBED 64
#define HID   128
#define MAXN  1000000
#define TILE_M 128
#define NTHREADS 512

// Scratch: messages[N, 64]. __device__ global (no allocation allowed).
__device__ float g_msgs[(size_t)MAXN * EMBED];

// ---------------------------------------------------------------------------
// Packed fp32x2 helpers (Blackwell FFMA2 path — PTX only, ptxas won't fuse)
// ---------------------------------------------------------------------------
__device__ __forceinline__ unsigned long long pk2(float x, float y) {
    unsigned long long r;
    asm("mov.b64 %0, {%1, %2};" : "=l"(r) : "f"(x), "f"(y));
    return r;
}
__device__ __forceinline__ void upk2(unsigned long long v, float& x, float& y) {
    asm("mov.b64 {%0, %1}, %2;" : "=f"(x), "=f"(y) : "l"(v));
}
__device__ __forceinline__ unsigned long long ffma2(unsigned long long a,
                                                    unsigned long long b,
                                                    unsigned long long c) {
    unsigned long long d;
    asm("fma.rn.f32x2 %0, %1, %2, %3;" : "=l"(d) : "l"(a), "l"(b), "l"(c));
    return d;
}

// ---------------------------------------------------------------------------
// Kernel 0: no-op probe (keeps ncu -s 5 -c 1 landing on the MLP kernel)
// ---------------------------------------------------------------------------
__global__ void probe_kernel(int x) { (void)x; }

// ---------------------------------------------------------------------------
// Kernel 1: zero the message buffer
// ---------------------------------------------------------------------------
__global__ void zero_msgs_kernel(int n4) {
    int i = blockIdx.x * blockDim.x + threadIdx.x;
    if (i < n4) reinterpret_cast<float4*>(g_msgs)[i] = make_float4(0.f, 0.f, 0.f, 0.f);
}

// ---------------------------------------------------------------------------
// Kernel 2: scatter-add  messages[dst] += emb[src]   (edge_index int32)
// 16 threads/edge, red.global.add.v4.f32 (no return trip).
// ---------------------------------------------------------------------------
__global__ void scatter_kernel(const int* __restrict__ ei,
                               const float* __restrict__ emb, int E) {
    long long idx = (long long)blockIdx.x * blockDim.x + threadIdx.x;
    if (idx >= (long long)E * 16) return;
    int e  = (int)(idx >> 4);
    int d4 = (int)(idx & 15);
    int src = ei[e];
    int dst = ei[E + e];
    float4 v = reinterpret_cast<const float4*>(emb + (size_t)src * EMBED)[d4];
    float* o = g_msgs + (size_t)dst * EMBED + d4 * 4;
    asm volatile("red.global.add.v4.f32 [%0], {%1, %2, %3, %4};"
                 :: "l"(o), "f"(v.x), "f"(v.y), "f"(v.z), "f"(v.w)
                 : "memory");
}

// ---------------------------------------------------------------------------
// Kernel 3: fused 2-layer MLP + residual, persistent FFMA2 GEMM.
// 512 threads = 16 warps (occ 25%).  Warp w:
//   wh = w & 7  -> h-block [16wh,16wh+16) (GEMM1) / n-block [8wh,8wh+8) (GEMM2)
//   mh = w >> 3 -> node-pair half; lane owns pair pp = lane + 32*mh
// Weight operand is warp-uniform (pure LDS.128 broadcast). Per-thread state:
// GEMM1 acc[16]+b[16] u64 (~70 regs), GEMM2 acc[8]+b[8].
// xs[k][m] / hs[k][m] rows = 512 B: LDS.64/STS.64 2-phase conflict-free.
// ---------------------------------------------------------------------------
__global__ void __launch_bounds__(NTHREADS) mlp_kernel(
    const float* __restrict__ emb,
    const float* __restrict__ w1, const float* __restrict__ b1,
    const float* __restrict__ w2, const float* __restrict__ b2,
    float* __restrict__ out, int N, int ntiles)
{
    extern __shared__ float smem[];
    float* xs  = smem;                 // [64][128]
    float* hs  = xs + 64 * 128;        // [128][128]
    float* w1d = hs + 128 * 128;       // [64][256]   {w,w} dup over h
    float* w2d = w1d + 64 * 256;       // [128][128]  {w,w} dup over n
    float* b1s = w2d + 128 * 128;      // [128]
    float* b2s = b1s + 128;            // [64]

    const int tid  = threadIdx.x;
    const int lane = tid & 31;
    const int wrp  = tid >> 5;
    const int wh   = wrp & 7;
    const int mh   = wrp >> 3;
    const int pp   = lane + 32 * mh;   // node-pair index 0..63

    // ---- stage duplicated weights + biases ONCE (persistent kernel) ----
    for (int i = tid; i < HID * EMBED; i += NTHREADS) {
        float v = w1[i];               // w1[h][d]
        int h = i >> 6, d = i & 63;
        w1d[d * 256 + 2 * h]     = v;
        w1d[d * 256 + 2 * h + 1] = v;
    }
    for (int i = tid; i < EMBED * HID; i += NTHREADS) {
        float v = w2[i];               // w2[n][h]
        int n = i >> 7, h = i & 127;
        w2d[h * 128 + 2 * n]     = v;
        w2d[h * 128 + 2 * n + 1] = v;
    }
    if (tid < HID)   b1s[tid] = b1[tid];
    if (tid < EMBED) b2s[tid] = b2[tid];

    const int h0 = wh * 16;
    const int n0 = wh * 8;
    unsigned long long* xsu = reinterpret_cast<unsigned long long*>(xs); // [64][64]
    unsigned long long* hsu = reinterpret_cast<unsigned long long*>(hs); // [128][64]

    for (int tile = blockIdx.x; tile < ntiles; tile += gridDim.x) {
        const int node0 = tile * TILE_M;

        // ---- stage msgs tile: xs[k][m] (lanes -> consecutive m, 0-conflict) ----
        #pragma unroll
        for (int j = 0; j < 4; j++) {
            int lin = tid + j * NTHREADS;
            int m  = lin & 127;
            int c4 = lin >> 7;         // 0..15
            int node = node0 + m;
            float4 v = make_float4(0.f, 0.f, 0.f, 0.f);
            if (node < N)
                v = reinterpret_cast<const float4*>(g_msgs + (size_t)node * EMBED)[c4];
            xs[(4 * c4 + 0) * 128 + m] = v.x;
            xs[(4 * c4 + 1) * 128 + m] = v.y;
            xs[(4 * c4 + 2) * 128 + m] = v.z;
            xs[(4 * c4 + 3) * 128 + m] = v.w;
        }
        __syncthreads();

        // ---------------- GEMM1: 1 pair x 16 h per thread ----------------
        {
            unsigned long long acc[16];
            #pragma unroll
            for (int j = 0; j < 16; j++) {
                float bb = b1s[h0 + j];
                acc[j] = pk2(bb, bb);
            }
            #pragma unroll 4
            for (int k = 0; k < EMBED; k++) {
                unsigned long long a = xsu[k * 64 + pp];
                const ulonglong2* bp =
                    reinterpret_cast<const ulonglong2*>(&w1d[k * 256 + 2 * h0]);
                unsigned long long b[16];
                #pragma unroll
                for (int r = 0; r < 8; r++) {      // warp-uniform broadcasts
                    ulonglong2 t = bp[r];
                    b[2 * r] = t.x; b[2 * r + 1] = t.y;
                }
                #pragma unroll
                for (int j = 0; j < 16; j++)
                    acc[j] = ffma2(a, b[j], acc[j]);
            }
            // relu -> hs[h][m] (STS.64, 2-phase conflict-free)
            #pragma unroll
            for (int j = 0; j < 16; j++) {
                float x, y;
                upk2(acc[j], x, y);
                hsu[(h0 + j) * 64 + pp] = pk2(fmaxf(x, 0.f), fmaxf(y, 0.f));
            }
        }
        __syncthreads();

        // ---------------- GEMM2: 1 pair x 8 n per thread ----------------
        {
            unsigned long long acc[8];
            #pragma unroll
            for (int n = 0; n < 8; n++) {
                float bb = b2s[n0 + n];
                acc[n] = pk2(bb, bb);
            }
            #pragma unroll 4
            for (int k = 0; k < HID; k++) {
                unsigned long long a = hsu[k * 64 + pp];
                const ulonglong2* bp =
                    reinterpret_cast<const ulonglong2*>(&w2d[k * 128 + 2 * n0]);
                unsigned long long b[8];
                #pragma unroll
                for (int r = 0; r < 4; r++) {      // warp-uniform broadcasts
                    ulonglong2 t = bp[r];
                    b[2 * r] = t.x; b[2 * r + 1] = t.y;
                }
                #pragma unroll
                for (int n = 0; n < 8; n++)
                    acc[n] = ffma2(a, b[n], acc[n]);
            }
            // epilogue: relu + residual; this thread owns nodes 2pp, 2pp+1,
            // output cols [n0, n0+8) -> two float4 per node
            float lo[8], hi[8];
            #pragma unroll
            for (int n = 0; n < 8; n++) upk2(acc[n], lo[n], hi[n]);
            #pragma unroll
            for (int p = 0; p < 2; p++) {
                int node = node0 + 2 * pp + p;
                if (node < N) {
                    const float* vv = p ? hi : lo;
                    const float4* ep = reinterpret_cast<const float4*>(
                        emb + (size_t)node * EMBED + n0);
                    float4* op = reinterpret_cast<float4*>(
                        out + (size_t)node * EMBED + n0);
                    float4 e0 = ep[0], e1 = ep[1];
                    float4 o0, o1;
                    o0.x = e0.x + fmaxf(vv[0], 0.f);
                    o0.y = e0.y + fmaxf(vv[1], 0.f);
                    o0.z = e0.z + fmaxf(vv[2], 0.f);
                    o0.w = e0.w + fmaxf(vv[3], 0.f);
                    o1.x = e1.x + fmaxf(vv[4], 0.f);
                    o1.y = e1.y + fmaxf(vv[5], 0.f);
                    o1.z = e1.z + fmaxf(vv[6], 0.f);
                    o1.w = e1.w + fmaxf(vv[7], 0.f);
                    op[0] = o0; op[1] = o1;
                }
            }
        }
        __syncthreads();   // xs/hs safe to overwrite next tile
    }
}

// ---------------------------------------------------------------------------
// Launch
// ---------------------------------------------------------------------------
extern "C" void kernel_launch(void* const* d_in, const int* in_sizes, int n_in,
                              void* d_out, int out_size) {
    const int*   ei  = (const int*)d_in[0];   // edge_index [2, E] int32
    const float* emb = (const float*)d_in[1]; // [N, 64]
    const float* w1  = (const float*)d_in[2]; // [128, 64]
    const float* b1  = (const float*)d_in[3]; // [128]
    const float* w2  = (const float*)d_in[4]; // [64, 128]
    const float* b2  = (const float*)d_in[5]; // [64]
    float*       out = (float*)d_out;

    int E = in_sizes[0] / 2;
    int N = in_sizes[1] / EMBED;

    static int nsm = 0;
    if (nsm == 0) {
        cudaDeviceGetAttribute(&nsm, cudaDevAttrMultiProcessorCount, 0);
        if (nsm <= 0) nsm = 148;
    }

    // 0) capture-alignment probe (no-op)
    probe_kernel<<<1, 32>>>(0);

    // 1) zero messages
    int n4 = N * (EMBED / 4);
    zero_msgs_kernel<<<(n4 + 255) / 256, 256>>>(n4);

    // 2) scatter-add
    long long total = (long long)E * 16;
    scatter_kernel<<<(unsigned)((total + 255) / 256), 256>>>(ei, emb, E);

    // 3) fused persistent FFMA2 MLP + residual (512 threads, 16 warps)
    static const int SMEM_BYTES =
        (64 * 128 + 128 * 128 + 64 * 256 + 128 * 128 + HID + EMBED)
        * (int)sizeof(float);                      // 230,144 B
    cudaFuncSetAttribute(mlp_kernel, cudaFuncAttributeMaxDynamicSharedMemorySize,
                         SMEM_BYTES);
    int ntiles = (N + TILE_M - 1) / TILE_M;
    mlp_kernel<<<nsm, NTHREADS, SMEM_BYTES>>>(emb, w1, b1, w2, b2, out, N, ntiles);
}

// round 9
// speedup vs baseline: 2.5977x; 2.5977x over previous
#include <cuda_runtime.h>
#include <cuda_bf16.h>
#include <cstdint>

#define EMBED 64
#define HID   128
#define MAXN  1000000
#define TILE_M 128
#define NTH   256

// Scratch: messages[N, 64]. __device__ global (no allocation allowed).
__device__ float g_msgs[(size_t)MAXN * EMBED];

// ---------------------------------------------------------------------------
// smem layout (bytes). x/w1 rows: 72 u16 (144 B, +4 banks/row -> ldmatrix
// conflict-free). hs/w2 rows: 136 u16 (272 B, same property).
// ---------------------------------------------------------------------------
#define STRX 72
#define STRH 136
#define OFF_XHI  0
#define OFF_XLO  (OFF_XHI  + 128*STRX*2)
#define OFF_W1HI (OFF_XLO  + 128*STRX*2)
#define OFF_W1LO (OFF_W1HI + 128*STRX*2)
#define OFF_W2HI (OFF_W1LO + 128*STRX*2)
#define OFF_W2LO (OFF_W2HI + 64*STRH*2)
#define OFF_HSHI (OFF_W2LO + 64*STRH*2)
#define OFF_HSLO (OFF_HSHI + 128*STRH*2)
#define OFF_B1   (OFF_HSLO + 128*STRH*2)
#define OFF_B2   (OFF_B1 + 128*4)
#define SMEM_TOT (OFF_B2 + 64*4)

// ---------------------------------------------------------------------------
// PTX helpers
// ---------------------------------------------------------------------------
__device__ __forceinline__ uint32_t smem_u32(const void* p) {
    uint32_t a;
    asm("{ .reg .u64 t; cvta.to.shared.u64 t, %1; cvt.u32.u64 %0, t; }"
        : "=r"(a) : "l"(p));
    return a;
}
__device__ __forceinline__ void ldm4(uint32_t r[4], uint32_t addr) {
    asm volatile("ldmatrix.sync.aligned.m8n8.x4.shared.b16 {%0,%1,%2,%3}, [%4];"
                 : "=r"(r[0]), "=r"(r[1]), "=r"(r[2]), "=r"(r[3]) : "r"(addr));
}
__device__ __forceinline__ void mma16816(float c[4], const uint32_t a[4],
                                         uint32_t b0, uint32_t b1) {
    asm volatile(
        "mma.sync.aligned.m16n8k16.row.col.f32.bf16.bf16.f32 "
        "{%0,%1,%2,%3}, {%4,%5,%6,%7}, {%8,%9}, {%0,%1,%2,%3};"
        : "+f"(c[0]), "+f"(c[1]), "+f"(c[2]), "+f"(c[3])
        : "r"(a[0]), "r"(a[1]), "r"(a[2]), "r"(a[3]), "r"(b0), "r"(b1));
}
// pack two f32 -> bf16x2 (d[31:16]=hi_src, d[15:0]=lo_src)
__device__ __forceinline__ uint32_t cvt2bf(float hi_src, float lo_src) {
    uint32_t r;
    asm("cvt.rn.bf16x2.f32 %0, %1, %2;" : "=r"(r) : "f"(hi_src), "f"(lo_src));
    return r;
}

// ---------------------------------------------------------------------------
// Kernel 0: no-op probe (keeps ncu -s 5 -c 1 landing on the MLP kernel)
// ---------------------------------------------------------------------------
__global__ void probe_kernel(int x) { (void)x; }

// ---------------------------------------------------------------------------
// Kernel 1: zero the message buffer
// ---------------------------------------------------------------------------
__global__ void zero_msgs_kernel(int n4) {
    int i = blockIdx.x * blockDim.x + threadIdx.x;
    if (i < n4) reinterpret_cast<float4*>(g_msgs)[i] = make_float4(0.f, 0.f, 0.f, 0.f);
}

// ---------------------------------------------------------------------------
// Kernel 2: scatter-add  messages[dst] += emb[src]   (edge_index int32)
// ---------------------------------------------------------------------------
__global__ void scatter_kernel(const int* __restrict__ ei,
                               const float* __restrict__ emb, int E) {
    long long idx = (long long)blockIdx.x * blockDim.x + threadIdx.x;
    if (idx >= (long long)E * 16) return;
    int e  = (int)(idx >> 4);
    int d4 = (int)(idx & 15);
    int src = ei[e];
    int dst = ei[E + e];
    float4 v = reinterpret_cast<const float4*>(emb + (size_t)src * EMBED)[d4];
    float* o = g_msgs + (size_t)dst * EMBED + d4 * 4;
    asm volatile("red.global.add.v4.f32 [%0], {%1, %2, %3, %4};"
                 :: "l"(o), "f"(v.x), "f"(v.y), "f"(v.z), "f"(v.w)
                 : "memory");
}

// ---------------------------------------------------------------------------
// Kernel 3: fused 2-layer MLP + residual on mma.sync bf16 (hi/lo split).
// Persistent, 256 threads = 8 warps; warp w owns node rows [16w, 16w+16).
//   GEMM1: acc[16 ntile][4] f32; A = x frag (ldmatrix), B = w1 frag;
//          products hi*hi + hi*lo + lo*hi accumulated in f32.
//   epi1 : +b1 (in acc init), relu, re-split -> hs hi/lo (bf16)
//   GEMM2: acc[8 ntile][4]; A = hs, B = w2, same 3 products.
//   epi2 : relu, + emb residual, float2 stores.
// ---------------------------------------------------------------------------
__global__ void __launch_bounds__(NTH) mlp_mma_kernel(
    const float* __restrict__ emb,
    const float* __restrict__ w1, const float* __restrict__ b1,
    const float* __restrict__ w2, const float* __restrict__ b2,
    float* __restrict__ out, int N, int ntiles)
{
    extern __shared__ char smem[];
    const uint32_t sb = smem_u32(smem);
    float* b1s = (float*)(smem + OFF_B1);
    float* b2s = (float*)(smem + OFF_B2);

    const int tid  = threadIdx.x;
    const int lane = tid & 31;
    const int wrp  = tid >> 5;          // 0..7
    const int mrow = wrp * 16;

    // ---- stage weights hi/lo ONCE ----
    for (int i = tid; i < HID * EMBED; i += NTH) {      // w1[h][d]
        float v = w1[i];
        int h = i >> 6, d = i & 63;
        __nv_bfloat16 hb = __float2bfloat16(v);
        __nv_bfloat16 lb = __float2bfloat16(v - __bfloat162float(hb));
        *(uint16_t*)(smem + OFF_W1HI + (h * STRX + d) * 2) = __bfloat16_as_ushort(hb);
        *(uint16_t*)(smem + OFF_W1LO + (h * STRX + d) * 2) = __bfloat16_as_ushort(lb);
    }
    for (int i = tid; i < EMBED * HID; i += NTH) {      // w2[n][k]
        float v = w2[i];
        int n = i >> 7, k = i & 127;
        __nv_bfloat16 hb = __float2bfloat16(v);
        __nv_bfloat16 lb = __float2bfloat16(v - __bfloat162float(hb));
        *(uint16_t*)(smem + OFF_W2HI + (n * STRH + k) * 2) = __bfloat16_as_ushort(hb);
        *(uint16_t*)(smem + OFF_W2LO + (n * STRH + k) * 2) = __bfloat16_as_ushort(lb);
    }
    if (tid < HID)   b1s[tid] = b1[tid];
    if (tid < EMBED) b2s[tid] = b2[tid];

    const int dcol = 2 * (lane & 3);    // D-frag col within 8-wide tile
    const int drow = lane >> 2;         // D-frag row within 16-tall tile

    for (int tile = blockIdx.x; tile < ntiles; tile += gridDim.x) {
        const int node0 = tile * TILE_M;

        // ---- stage x tile: f32 -> bf16 hi/lo ----
        #pragma unroll
        for (int j = 0; j < 8; j++) {
            int lin = tid + j * NTH;      // 2048 float4 units
            int c4 = lin & 15, m = lin >> 4;
            int node = node0 + m;
            float4 v = make_float4(0.f, 0.f, 0.f, 0.f);
            if (node < N)
                v = reinterpret_cast<const float4*>(g_msgs + (size_t)node * EMBED)[c4];
            uint32_t p01 = cvt2bf(v.y, v.x);
            uint32_t p23 = cvt2bf(v.w, v.z);
            float h0 = __uint_as_float(p01 << 16);
            float h1 = __uint_as_float(p01 & 0xffff0000u);
            float h2 = __uint_as_float(p23 << 16);
            float h3 = __uint_as_float(p23 & 0xffff0000u);
            uint32_t l01 = cvt2bf(v.y - h1, v.x - h0);
            uint32_t l23 = cvt2bf(v.w - h3, v.z - h2);
            uint32_t off = (uint32_t)(m * STRX + c4 * 4) * 2;  // bytes
            *(uint2*)(smem + OFF_XHI + off) = make_uint2(p01, p23);
            *(uint2*)(smem + OFF_XLO + off) = make_uint2(l01, l23);
        }
        __syncthreads();

        // ---------------- GEMM1: 16 m x 128 h per warp ----------------
        float acc[16][4];
        #pragma unroll
        for (int nt = 0; nt < 16; nt++) {
            float bb0 = b1s[nt * 8 + dcol], bb1 = b1s[nt * 8 + dcol + 1];
            acc[nt][0] = bb0; acc[nt][1] = bb1; acc[nt][2] = bb0; acc[nt][3] = bb1;
        }
        {
            const uint32_t a_off = (uint32_t)((mrow + (lane & 15)) * STRX) * 2
                                   + (uint32_t)(lane >> 4) * 16;
            #pragma unroll
            for (int ks = 0; ks < 4; ks++) {
                uint32_t ahi[4], alo[4];
                ldm4(ahi, sb + OFF_XHI + a_off + ks * 32);
                ldm4(alo, sb + OFF_XLO + a_off + ks * 32);
                const uint32_t b_lane = (uint32_t)(lane & 15) * (STRX * 2)
                                        + (uint32_t)(lane >> 4) * 16 + ks * 32;
                #pragma unroll
                for (int pr = 0; pr < 8; pr++) {
                    uint32_t bh[4], bl[4];
                    uint32_t boff = (uint32_t)(pr * 16) * (STRX * 2) + b_lane;
                    ldm4(bh, sb + OFF_W1HI + boff);
                    ldm4(bl, sb + OFF_W1LO + boff);
                    mma16816(acc[2*pr],   ahi, bh[0], bh[2]);
                    mma16816(acc[2*pr],   ahi, bl[0], bl[2]);
                    mma16816(acc[2*pr],   alo, bh[0], bh[2]);
                    mma16816(acc[2*pr+1], ahi, bh[1], bh[3]);
                    mma16816(acc[2*pr+1], ahi, bl[1], bl[3]);
                    mma16816(acc[2*pr+1], alo, bh[1], bh[3]);
                }
            }
        }
        // ---- epi1: relu, split -> hs ----
        #pragma unroll
        for (int nt = 0; nt < 16; nt++) {
            float f0 = fmaxf(acc[nt][0], 0.f), f1 = fmaxf(acc[nt][1], 0.f);
            float f2 = fmaxf(acc[nt][2], 0.f), f3 = fmaxf(acc[nt][3], 0.f);
            uint32_t ph0 = cvt2bf(f1, f0);
            uint32_t ph1 = cvt2bf(f3, f2);
            float h0 = __uint_as_float(ph0 << 16);
            float h1 = __uint_as_float(ph0 & 0xffff0000u);
            float h2 = __uint_as_float(ph1 << 16);
            float h3 = __uint_as_float(ph1 & 0xffff0000u);
            uint32_t pl0 = cvt2bf(f1 - h1, f0 - h0);
            uint32_t pl1 = cvt2bf(f3 - h3, f2 - h2);
            int col = nt * 8 + dcol;
            uint32_t o0 = (uint32_t)((mrow + drow) * STRH + col) * 2;
            uint32_t o1 = (uint32_t)((mrow + drow + 8) * STRH + col) * 2;
            *(uint32_t*)(smem + OFF_HSHI + o0) = ph0;
            *(uint32_t*)(smem + OFF_HSLO + o0) = pl0;
            *(uint32_t*)(smem + OFF_HSHI + o1) = ph1;
            *(uint32_t*)(smem + OFF_HSLO + o1) = pl1;
        }
        __syncthreads();

        // ---------------- GEMM2: 16 m x 64 n per warp ----------------
        float acc2[8][4];
        #pragma unroll
        for (int nt = 0; nt < 8; nt++) {
            float bb0 = b2s[nt * 8 + dcol], bb1 = b2s[nt * 8 + dcol + 1];
            acc2[nt][0] = bb0; acc2[nt][1] = bb1; acc2[nt][2] = bb0; acc2[nt][3] = bb1;
        }
        {
            const uint32_t a_off = (uint32_t)((mrow + (lane & 15)) * STRH) * 2
                                   + (uint32_t)(lane >> 4) * 16;
            #pragma unroll
            for (int ks = 0; ks < 8; ks++) {
                uint32_t ahi[4], alo[4];
                ldm4(ahi, sb + OFF_HSHI + a_off + ks * 32);
                ldm4(alo, sb + OFF_HSLO + a_off + ks * 32);
                const uint32_t b_lane = (uint32_t)(lane & 15) * (STRH * 2)
                                        + (uint32_t)(lane >> 4) * 16 + ks * 32;
                #pragma unroll
                for (int pr = 0; pr < 4; pr++) {
                    uint32_t bh[4], bl[4];
                    uint32_t boff = (uint32_t)(pr * 16) * (STRH * 2) + b_lane;
                    ldm4(bh, sb + OFF_W2HI + boff);
                    ldm4(bl, sb + OFF_W2LO + boff);
                    mma16816(acc2[2*pr],   ahi, bh[0], bh[2]);
                    mma16816(acc2[2*pr],   ahi, bl[0], bl[2]);
                    mma16816(acc2[2*pr],   alo, bh[0], bh[2]);
                    mma16816(acc2[2*pr+1], ahi, bh[1], bh[3]);
                    mma16816(acc2[2*pr+1], ahi, bl[1], bl[3]);
                    mma16816(acc2[2*pr+1], alo, bh[1], bh[3]);
                }
            }
        }
        // ---- epi2: relu + residual, float2 stores ----
        {
            int r0 = node0 + mrow + drow;
            int r1 = r0 + 8;
            #pragma unroll
            for (int nt = 0; nt < 8; nt++) {
                int n = nt * 8 + dcol;
                if (r0 < N) {
                    float2 e = *(const float2*)(emb + (size_t)r0 * EMBED + n);
                    float2 o;
                    o.x = e.x + fmaxf(acc2[nt][0], 0.f);
                    o.y = e.y + fmaxf(acc2[nt][1], 0.f);
                    *(float2*)(out + (size_t)r0 * EMBED + n) = o;
                }
                if (r1 < N) {
                    float2 e = *(const float2*)(emb + (size_t)r1 * EMBED + n);
                    float2 o;
                    o.x = e.x + fmaxf(acc2[nt][2], 0.f);
                    o.y = e.y + fmaxf(acc2[nt][3], 0.f);
                    *(float2*)(out + (size_t)r1 * EMBED + n) = o;
                }
            }
        }
        __syncthreads();   // xs/hs safe to overwrite next tile
    }
}

// ---------------------------------------------------------------------------
// Launch
// ---------------------------------------------------------------------------
extern "C" void kernel_launch(void* const* d_in, const int* in_sizes, int n_in,
                              void* d_out, int out_size) {
    const int*   ei  = (const int*)d_in[0];   // edge_index [2, E] int32
    const float* emb = (const float*)d_in[1]; // [N, 64]
    const float* w1  = (const float*)d_in[2]; // [128, 64]
    const float* b1  = (const float*)d_in[3]; // [128]
    const float* w2  = (const float*)d_in[4]; // [64, 128]
    const float* b2  = (const float*)d_in[5]; // [64]
    float*       out = (float*)d_out;

    int E = in_sizes[0] / 2;
    int N = in_sizes[1] / EMBED;

    static int nsm = 0;
    if (nsm == 0) {
        cudaDeviceGetAttribute(&nsm, cudaDevAttrMultiProcessorCount, 0);
        if (nsm <= 0) nsm = 148;
    }

    // 0) capture-alignment probe (no-op)
    probe_kernel<<<1, 32>>>(0);

    // 1) zero messages
    int n4 = N * (EMBED / 4);
    zero_msgs_kernel<<<(n4 + 255) / 256, 256>>>(n4);

    // 2) scatter-add
    long long total = (long long)E * 16;
    scatter_kernel<<<(unsigned)((total + 255) / 256), 256>>>(ei, emb, E);

    // 3) tensor-core (mma.sync) fused MLP + residual
    cudaFuncSetAttribute(mlp_mma_kernel, cudaFuncAttributeMaxDynamicSharedMemorySize,
                         SMEM_TOT);
    int ntiles = (N + TILE_M - 1) / TILE_M;
    mlp_mma_kernel<<<nsm, NTH, SMEM_TOT>>>(emb, w1, b1, w2, b2, out, N, ntiles);
}